// round 13
// baseline (speedup 1.0000x reference)
#include <cuda_runtime.h>
#include <cstdint>

#define NTOK   524288     // 16*32*32*32
#define BATCH  32
#define ROWS   64         // 2 sides * 32 batch
#define NB1    8192       // buckets: float bits >> 19
#define SMARG  640u       // sample-rank margin at 1/16 sampling (true ranks: *16 = 10240)
#define NSEG   8          // candidate segments per row (= k_mask chunks)
#define CAPB   8192       // per-segment candidate capacity
#define BUFCAP 12288      // per-block smem candidate buffer
#define SELC   24576      // smem-resident (key+idx) cap in k_select

static __device__ __forceinline__ float clampf(float x) {
    return fminf(fmaxf(x, 1e-3f), 0.999f);
}

// ---------------- scratch ----------------
__device__ float        d_tab[2][BATCH][112];         // Ev[16] Et[32] Eh[32] Ew[32]
__device__ int          d_Kc[2];
__device__ int          d_bHi[ROWS];
__device__ int          d_bLo[ROWS];
__device__ unsigned int d_abovePart[ROWS][NSEG];
__device__ unsigned int d_ccPart[ROWS][NSEG];
__device__ unsigned int d_candKey[ROWS][NSEG * CAPB]; // 16 MB
__device__ unsigned int d_candIdx[ROWS][NSEG * CAPB]; // 16 MB

// ---------------- k_histscan: tables + sampled hist (1/16) + suffix scan, 1 block/row ----------------
// Sample: for each (v,t) cell (512 cells), 2 groups of 32 consecutive tokens,
// h rotated per (v,t,j). 512*2*32 = 32768 samples/row = 1/16.
__global__ void __launch_bounds__(1024) k_histscan(
    const float* __restrict__ comps, const int* __restrict__ idxp,
    const float* __restrict__ ur_s, const float* __restrict__ ur_t,
    const float* __restrict__ uv_s, const float* __restrict__ ut_s,
    const float* __restrict__ uh_s, const float* __restrict__ uw_s,
    const float* __restrict__ uv_t, const float* __restrict__ ut_t,
    const float* __restrict__ uh_t, const float* __restrict__ uw_t,
    const float* __restrict__ u0s, const float* __restrict__ u0t)
{
    __shared__ unsigned int sh[NB1];
    __shared__ float stab[112];
    __shared__ unsigned int wsum[32];
    __shared__ unsigned int stot;
    int row  = blockIdx.x;
    int side = row >> 5, b = row & 31;
    int t = threadIdx.x;
    for (int i = t; i < NB1; i += 1024) sh[i] = 0u;

    // compute this row's pow-table (also publish for k_mask)
    if (t < 112) {
        int id = idxp[0];
        const float* uv = side ? uv_t : uv_s;
        const float* ut = side ? ut_t : ut_s;
        const float* uh = side ? uh_t : uh_s;
        const float* uw = side ? uw_t : uw_s;
        float val, ia;
        if (t < 16)      { val = uv[b*16 +  t     ]; ia = 1.0f / comps[id*4+0]; }
        else if (t < 48) { val = ut[b*32 + (t-16)]; ia = 1.0f / comps[id*4+1]; }
        else if (t < 80) { val = uh[b*32 + (t-48)]; ia = 1.0f / comps[id*4+2]; }
        else             { val = uw[b*32 + (t-80)]; ia = 1.0f / comps[id*4+3]; }
        float e = powf(clampf(val), ia);
        stab[t] = e;
        d_tab[side][b][t] = e;
    }
    if (row == 0 && t == 0) d_Kc[0] = (int)(clampf(ur_s[0]) * (float)NTOK);
    if (row == 0 && t == 1) d_Kc[1] = (int)(clampf(ur_t[0]) * (float)NTOK);
    __syncthreads();

    const float4* src = (const float4*)((side ? u0t : u0s) + (size_t)b * NTOK);
    int q = t & 3;
    int w = q * 8;

    // g in [0,1024): v = g>>6, tt = (g>>1)&31, j = g&1, h = (v*3 + tt*5 + j*16)&31
    auto chunk_b4 = [&](int ch) -> int {
        int g  = ch * 256 + (t >> 2);
        int v  = g >> 6, tt = (g >> 1) & 31, j = g & 1;
        int h  = (v*3 + tt*5 + j*16) & 31;
        return ((((v << 5) | tt) << 5) | h) * 8 + q * 2;
    };
    auto chunk_pre = [&](int ch) -> float {
        int g  = ch * 256 + (t >> 2);
        int v  = g >> 6, tt = (g >> 1) & 31, j = g & 1;
        int h  = (v*3 + tt*5 + j*16) & 31;
        return stab[v] * stab[16+tt] * stab[48+h];
    };

    // depth-2 register pipeline over 4 chunks
    int b40 = chunk_b4(0);
    float4 A0 = src[b40];
    float4 C0 = src[b40 + 1];
    int b41 = chunk_b4(1);
    float4 A1 = src[b41];
    float4 C1 = src[b41 + 1];
    float pre0 = chunk_pre(0);
    float pre1 = chunk_pre(1);

    for (int ch = 0; ch < 4; ch++) {
        float4 A2, C2;
        float pre2 = 0.0f;
        if (ch + 2 < 4) {
            int b4 = chunk_b4(ch + 2);
            A2 = src[b4];
            C2 = src[b4 + 1];
            pre2 = chunk_pre(ch + 2);
        }

        float pre = pre0;
        float k0 = clampf(A0.x) * pre * stab[80+w+0];
        float k1 = clampf(A0.y) * pre * stab[80+w+1];
        float k2 = clampf(A0.z) * pre * stab[80+w+2];
        float k3 = clampf(A0.w) * pre * stab[80+w+3];
        float k4 = clampf(C0.x) * pre * stab[80+w+4];
        float k5 = clampf(C0.y) * pre * stab[80+w+5];
        float k6 = clampf(C0.z) * pre * stab[80+w+6];
        float k7 = clampf(C0.w) * pre * stab[80+w+7];
        atomicAdd(&sh[__float_as_uint(k0) >> 19], 1u);
        atomicAdd(&sh[__float_as_uint(k1) >> 19], 1u);
        atomicAdd(&sh[__float_as_uint(k2) >> 19], 1u);
        atomicAdd(&sh[__float_as_uint(k3) >> 19], 1u);
        atomicAdd(&sh[__float_as_uint(k4) >> 19], 1u);
        atomicAdd(&sh[__float_as_uint(k5) >> 19], 1u);
        atomicAdd(&sh[__float_as_uint(k6) >> 19], 1u);
        atomicAdd(&sh[__float_as_uint(k7) >> 19], 1u);

        A0 = A1; C0 = C1; pre0 = pre1;
        A1 = A2; C1 = C2; pre1 = pre2;
    }
    __syncthreads();

    // suffix scan over descending buckets
    unsigned int v[8]; unsigned int s = 0;
    #pragma unroll
    for (int i = 0; i < 8; i++) { v[i] = sh[8191 - (t*8 + i)]; s += v[i]; }
    unsigned int x = s;
    int lane = t & 31, wp = t >> 5;
    #pragma unroll
    for (int o = 1; o < 32; o <<= 1) {
        unsigned int y = __shfl_up_sync(0xffffffffu, x, o);
        if (lane >= o) x += y;
    }
    if (lane == 31) wsum[wp] = x;
    __syncthreads();
    if (t < 32) {
        unsigned int y = wsum[t], z = y;
        #pragma unroll
        for (int o = 1; o < 32; o <<= 1) {
            unsigned int qq = __shfl_up_sync(0xffffffffu, z, o);
            if (t >= o) z += qq;
        }
        wsum[t] = z - y;                 // exclusive warp prefix
        if (t == 31) stot = z;
    }
    __syncthreads();
    unsigned int P = wsum[wp] + x - s;   // samples strictly above this thread's chunk
    float urv = side ? ur_t[0] : ur_s[0];
    unsigned int K = (unsigned int)(int)(clampf(urv) * (float)NTOK);
    unsigned int sKt = K >> 4;           // sample fraction exactly 1/16
    unsigned int targHi = (sKt > SMARG) ? (sKt - SMARG) : 0u;
    unsigned int targLo = sKt + SMARG;
    unsigned int total = stot;
    unsigned int cum = P;
    #pragma unroll
    for (int i = 0; i < 8; i++) {
        int bb = 8191 - (t*8 + i);
        unsigned int hv = v[i];
        if (cum <= targHi && cum + hv > targHi) d_bHi[row] = bb;
        if (cum <  targLo && cum + hv >= targLo) d_bLo[row] = bb;
        cum += hv;
    }
    if (t == 0 && targLo > total) d_bLo[row] = 0;
}

// ---------------- k_mask: pipelined loads, aggregated append, single end-flush ----------------
extern __shared__ unsigned int mbuf[];
__global__ void __launch_bounds__(512, 2) k_mask(const float* __restrict__ u0s,
                                                 const float* __restrict__ u0t,
                                                 float* __restrict__ out)
{
    __shared__ float stab[112];
    __shared__ unsigned int s17[17];
    __shared__ unsigned int sCnt;
    unsigned int* bKey = mbuf;
    unsigned int* bIdx = mbuf + BUFCAP;

    int row   = blockIdx.x >> 3;
    int chunk = blockIdx.x & 7;
    int side  = row >> 5, b = row & 31;
    int t = threadIdx.x;
    if (t < 112) stab[t] = d_tab[side][b][t];
    if (t == 0) sCnt = 0u;
    __syncthreads();

    unsigned int bHi = (unsigned int)d_bHi[row];
    unsigned int bLo = (unsigned int)d_bLo[row];
    unsigned long long hk = ((unsigned long long)(bHi + 1)) << 19;
    float Thif = (hk >= 0x3F800000ull) ? 1.0f : __uint_as_float((unsigned int)hk);
    float Tlof = __uint_as_float(bLo << 19);

    const float4* src = (const float4*)((side ? u0t : u0s) + (size_t)b * NTOK);
    float4* out4 = (float4*)(out + (size_t)row * NTOK);
    unsigned int* segK = &d_candKey[row][chunk * CAPB];
    unsigned int* segI = &d_candIdx[row][chunk * CAPB];
    int lane = t & 31;
    unsigned int lmask = (1u << lane) - 1u;
    unsigned int nAbove = 0;

    int w0 = (t << 2) & 31;
    int h  = (t >> 3) & 31;
    float hC = stab[48 + h];
    float wj0 = stab[80+w0+0] * hC;
    float wj1 = stab[80+w0+1] * hC;
    float wj2 = stab[80+w0+2] * hC;
    float wj3 = stab[80+w0+3] * hC;

#define PROC(u, idx4) do {                                                          \
    float pre = stab[(idx4) >> 13] * stab[16 + (((idx4) >> 8) & 31)];               \
    float k0 = clampf((u).x) * pre * wj0;                                           \
    float k1 = clampf((u).y) * pre * wj1;                                           \
    float k2 = clampf((u).z) * pre * wj2;                                           \
    float k3 = clampf((u).w) * pre * wj3;                                           \
    bool a0 = (k0 >= Thif), a1 = (k1 >= Thif), a2 = (k2 >= Thif), a3 = (k3 >= Thif);\
    nAbove += (unsigned int)a0 + a1 + a2 + a3;                                      \
    unsigned int cm = (unsigned int)(!a0 && k0 >= Tlof)                             \
                    | ((unsigned int)(!a1 && k1 >= Tlof) << 1)                      \
                    | ((unsigned int)(!a2 && k2 >= Tlof) << 2)                      \
                    | ((unsigned int)(!a3 && k3 >= Tlof) << 3);                     \
    unsigned int b0 = __ballot_sync(0xffffffffu, cm & 1u);                          \
    unsigned int b1 = __ballot_sync(0xffffffffu, cm & 2u);                          \
    unsigned int b2 = __ballot_sync(0xffffffffu, cm & 4u);                          \
    unsigned int b3 = __ballot_sync(0xffffffffu, cm & 8u);                          \
    unsigned int c0 = __popc(b0), c1 = __popc(b1), c2 = __popc(b2), c3 = __popc(b3);\
    unsigned int tot = c0 + c1 + c2 + c3;                                           \
    if (tot) {                                                                      \
        unsigned int bp = 0;                                                        \
        if (lane == 0) bp = atomicAdd(&sCnt, tot);                                  \
        bp = __shfl_sync(0xffffffffu, bp, 0);                                       \
        int n = (idx4) << 2;                                                        \
        if (cm & 1u) { unsigned int p = bp + __popc(b0 & lmask);                    \
            if (p < BUFCAP) { bKey[p] = __float_as_uint(k0); bIdx[p] = (unsigned int)n; } } \
        if (cm & 2u) { unsigned int p = bp + c0 + __popc(b1 & lmask);               \
            if (p < BUFCAP) { bKey[p] = __float_as_uint(k1); bIdx[p] = (unsigned int)(n + 1); } } \
        if (cm & 4u) { unsigned int p = bp + c0 + c1 + __popc(b2 & lmask);          \
            if (p < BUFCAP) { bKey[p] = __float_as_uint(k2); bIdx[p] = (unsigned int)(n + 2); } } \
        if (cm & 8u) { unsigned int p = bp + c0 + c1 + c2 + __popc(b3 & lmask);     \
            if (p < BUFCAP) { bKey[p] = __float_as_uint(k3); bIdx[p] = (unsigned int)(n + 3); } } \
    }                                                                               \
    __stcs(&out4[(idx4)], make_float4(a0 ? 1.0f : 0.0f, a1 ? 1.0f : 0.0f,           \
                                      a2 ? 1.0f : 0.0f, a3 ? 1.0f : 0.0f));         \
} while (0)

    int base4 = chunk * 16384;

    // prologue: load group 0
    int i0 = base4 + t;
    float4 u0 = __ldcs(&src[i0]);
    float4 u1 = __ldcs(&src[i0 + 512]);
    float4 u2 = __ldcs(&src[i0 + 1024]);
    float4 u3 = __ldcs(&src[i0 + 1536]);

    for (int itg = 0; itg < 8; itg++) {
        int j0 = base4 + (itg + 1) * 2048 + t;
        float4 n0, n1, n2, n3;
        if (itg < 7) { n0 = __ldcs(&src[j0]); n1 = __ldcs(&src[j0 + 512]); }
        PROC(u0, i0);
        PROC(u1, i0 + 512);
        if (itg < 7) { n2 = __ldcs(&src[j0 + 1024]); n3 = __ldcs(&src[j0 + 1536]); }
        PROC(u2, i0 + 1024);
        PROC(u3, i0 + 1536);
        u0 = n0; u1 = n1; u2 = n2; u3 = n3;
        i0 = j0;
    }
#undef PROC

    // single flush at end (per-chunk candidates ~2.6K mean, 100+ sigma below BUFCAP)
    __syncthreads();
    unsigned int cur = sCnt;
    if (cur > BUFCAP) cur = BUFCAP;
    for (unsigned int i = t; i < cur; i += 512) {
        if (i < CAPB) { segK[i] = bKey[i]; segI[i] = bIdx[i]; }
    }

    unsigned int wv = __reduce_add_sync(0xffffffffu, nAbove);
    if (lane == 0) s17[t >> 5] = wv;
    __syncthreads();
    if (t < 16) {
        unsigned int z = s17[t];
        #pragma unroll
        for (int o = 8; o > 0; o >>= 1) z += __shfl_down_sync(0xffffu, z, o);
        if (t == 0) d_abovePart[row][chunk] = z;
    }
    if (t == 16) d_ccPart[row][chunk] = (cur < CAPB) ? cur : CAPB;
}

// ---------------- block reduce helper (fallback path only) ----------------
static __device__ __forceinline__ unsigned int blk_reduce_1024(unsigned int v, unsigned int* s33)
{
    unsigned int wv = __reduce_add_sync(0xffffffffu, v);
    int lane = threadIdx.x & 31, w = threadIdx.x >> 5;
    __syncthreads();
    if (lane == 0) s33[w] = wv;
    __syncthreads();
    if (threadIdx.x < 32) {
        unsigned int x = s33[threadIdx.x];
        x = __reduce_add_sync(0xffffffffu, x);
        if (threadIdx.x == 0) s33[32] = x;
    }
    __syncthreads();
    return s33[32];
}

// ---------------- k_select: smem-resident keys+idx, radix descent + tie-break ----------------
extern __shared__ unsigned int dynsm[];
__global__ void __launch_bounds__(1024) k_select(float* __restrict__ out)
{
    __shared__ unsigned int hcnt[1024];
    __shared__ unsigned int wsum[32];
    __shared__ unsigned int sSel, sRnew;
    __shared__ unsigned int eqIdx[2048];
    __shared__ unsigned int eqCnt;
    __shared__ unsigned int sIstar;
    __shared__ unsigned int s33[33];
    unsigned int* keys = dynsm;
    unsigned int* idxs = dynsm + SELC;

    int row = blockIdx.x, t = threadIdx.x;
    unsigned int cnt[NSEG], off[NSEG];
    unsigned int c = 0, above = 0;
    #pragma unroll
    for (int s = 0; s < NSEG; s++) {
        unsigned int cs = d_ccPart[row][s];
        cnt[s] = (cs < CAPB) ? cs : CAPB;
        off[s] = c;
        c += cnt[s];
        above += d_abovePart[row][s];
    }
    unsigned int K = (unsigned int)d_Kc[row >> 5];
    int R = (int)K - (int)above;
    const unsigned int* gk = d_candKey[row];
    const unsigned int* gi = d_candIdx[row];
    float* orow = out + (size_t)row * NTOK;
    if (R <= 0) return;
    if ((unsigned int)R >= c) {
        #pragma unroll
        for (int s = 0; s < NSEG; s++)
            for (unsigned int i = t; i < cnt[s]; i += 1024)
                orow[gi[s*CAPB + i]] = 1.0f;
        return;
    }

    bool insm = (c <= SELC);
    if (insm) {
        #pragma unroll
        for (int s = 0; s < NSEG; s++)
            for (unsigned int i = t; i < cnt[s]; i += 1024) {
                keys[off[s] + i] = gk[s*CAPB + i];
                idxs[off[s] + i] = gi[s*CAPB + i];
            }
        __syncthreads();
    }

    unsigned int bLo = (unsigned int)d_bLo[row], bHi = (unsigned int)d_bHi[row];
    unsigned int base = bLo << 19;
    unsigned long long Wd = ((unsigned long long)(bHi + 1u - bLo)) << 19;
    int sb = (Wd <= 1ull) ? 0 : (64 - __clzll(Wd - 1ull));
    if (sb > 32) sb = 32;
    unsigned int Rcur = (unsigned int)R;

    while (sb > 0) {
        int bits = sb >= 10 ? 10 : sb;
        int shift = sb - bits;
        hcnt[t] = 0u;
        __syncthreads();
        unsigned int spanm = (sb >= 32) ? 0xFFFFFFFFu : ((1u << sb) - 1u);
        if (insm) {
            for (unsigned int i = t; i < c; i += 1024) {
                unsigned int k = keys[i];
                unsigned int d = k - base;
                if (k >= base && d <= spanm) atomicAdd(&hcnt[d >> shift], 1u);
            }
        } else {
            #pragma unroll
            for (int s = 0; s < NSEG; s++)
                for (unsigned int i = t; i < cnt[s]; i += 1024) {
                    unsigned int k = gk[s*CAPB + i];
                    unsigned int d = k - base;
                    if (k >= base && d <= spanm) atomicAdd(&hcnt[d >> shift], 1u);
                }
        }
        __syncthreads();
        unsigned int x = hcnt[1023 - t];
        unsigned int cb = x;
        int lane = t & 31, w = t >> 5;
        #pragma unroll
        for (int o = 1; o < 32; o <<= 1) {
            unsigned int y = __shfl_up_sync(0xffffffffu, x, o);
            if (lane >= o) x += y;
        }
        if (lane == 31) wsum[w] = x;
        __syncthreads();
        if (t < 32) {
            unsigned int y = wsum[t], z = y;
            #pragma unroll
            for (int o = 1; o < 32; o <<= 1) {
                unsigned int q = __shfl_up_sync(0xffffffffu, z, o);
                if (t >= o) z += q;
            }
            wsum[t] = z - y;
        }
        __syncthreads();
        unsigned int incl = wsum[w] + x;
        unsigned int A = incl - cb;
        if (A < Rcur && Rcur <= incl) { sSel = (unsigned int)(1023 - t); sRnew = Rcur - A; }
        __syncthreads();
        base += sSel << shift;
        Rcur = sRnew;
        sb = shift;
        __syncthreads();
    }
    unsigned int Tkey = base;
    unsigned int R3 = Rcur;   // rank among equal keys (stable by index), >= 1

    if (t == 0) eqCnt = 0u;
    __syncthreads();
    if (insm) {
        for (unsigned int i = t; i < c; i += 1024)
            if (keys[i] == Tkey) {
                unsigned int p = atomicAdd(&eqCnt, 1u);
                if (p < 2048) eqIdx[p] = idxs[i];
            }
    } else {
        #pragma unroll
        for (int s = 0; s < NSEG; s++)
            for (unsigned int i = t; i < cnt[s]; i += 1024)
                if (gk[s*CAPB + i] == Tkey) {
                    unsigned int p = atomicAdd(&eqCnt, 1u);
                    if (p < 2048) eqIdx[p] = gi[s*CAPB + i];
                }
    }
    __syncthreads();
    unsigned int e = eqCnt;
    unsigned int Istar;
    if (e <= 2048) {
        for (unsigned int j = t; j < e; j += 1024) {
            unsigned int my = eqIdx[j], r = 0;
            for (unsigned int m = 0; m < e; m++) r += (eqIdx[m] < my);
            if (r == R3 - 1u) sIstar = my;
        }
        __syncthreads();
        Istar = sIstar;
    } else {
        unsigned int ilo = 0, ihi = NTOK - 1;
        while (ilo < ihi) {
            unsigned int mid = (ilo + ihi) >> 1;
            unsigned int l2 = 0;
            if (insm) {
                for (unsigned int i = t; i < c; i += 1024)
                    if (keys[i] == Tkey) l2 += (idxs[i] <= mid);
            } else {
                #pragma unroll
                for (int s = 0; s < NSEG; s++)
                    for (unsigned int i = t; i < cnt[s]; i += 1024)
                        if (gk[s*CAPB + i] == Tkey) l2 += (gi[s*CAPB + i] <= mid);
            }
            unsigned int cc2 = blk_reduce_1024(l2, s33);
            if (cc2 >= R3) ihi = mid; else ilo = mid + 1u;
        }
        Istar = ilo;
    }

    if (insm) {
        for (unsigned int i = t; i < c; i += 1024) {
            unsigned int k = keys[i];
            if (k > Tkey || (k == Tkey && idxs[i] <= Istar)) orow[idxs[i]] = 1.0f;
        }
    } else {
        #pragma unroll
        for (int s = 0; s < NSEG; s++)
            for (unsigned int i = t; i < cnt[s]; i += 1024) {
                unsigned int k = gk[s*CAPB + i];
                if (k > Tkey || (k == Tkey && gi[s*CAPB + i] <= Istar))
                    orow[gi[s*CAPB + i]] = 1.0f;
            }
    }
}

// ---------------- launch ----------------
extern "C" void kernel_launch(void* const* d_in, const int* in_sizes, int n_in,
                              void* d_out, int out_size)
{
    const float* comps = (const float*)d_in[0];
    const float* ur_s  = (const float*)d_in[1];
    const float* ur_t  = (const float*)d_in[2];
    const float* u0s   = (const float*)d_in[3];
    const float* u0t   = (const float*)d_in[4];
    const float* uv_s  = (const float*)d_in[5];
    const float* ut_s  = (const float*)d_in[6];
    const float* uh_s  = (const float*)d_in[7];
    const float* uw_s  = (const float*)d_in[8];
    const float* uv_t  = (const float*)d_in[9];
    const float* ut_t  = (const float*)d_in[10];
    const float* uh_t  = (const float*)d_in[11];
    const float* uw_t  = (const float*)d_in[12];
    const int*   idx   = (const int*)d_in[13];
    float* out = (float*)d_out;

    static int attr_done = 0;
    if (!attr_done) {
        cudaFuncSetAttribute(k_mask, cudaFuncAttributeMaxDynamicSharedMemorySize,
                             BUFCAP * 2 * sizeof(unsigned int));
        cudaFuncSetAttribute(k_select, cudaFuncAttributeMaxDynamicSharedMemorySize,
                             SELC * 2 * sizeof(unsigned int));
        attr_done = 1;
    }

    k_histscan<<<64, 1024>>>(comps, idx, ur_s, ur_t,
                             uv_s, ut_s, uh_s, uw_s,
                             uv_t, ut_t, uh_t, uw_t,
                             u0s, u0t);
    k_mask<<<512, 512, BUFCAP * 2 * sizeof(unsigned int)>>>(u0s, u0t, out);
    k_select<<<64, 1024, SELC * 2 * sizeof(unsigned int)>>>(out);
}

// round 14
// speedup vs baseline: 1.2241x; 1.2241x over previous
#include <cuda_runtime.h>
#include <cstdint>

#define NTOK   524288     // 16*32*32*32
#define BATCH  32
#define ROWS   64         // 2 sides * 32 batch
#define NB1    8192       // buckets: float bits >> 19
#define SMARG  1024u      // sample-rank margin at 1/8 sampling (true ranks: *8 = 8192)
#define NSEG   8          // candidate segments per row (= k_mask chunks)
#define CAPB   8192       // per-segment candidate capacity
#define BUFCAP 12288      // per-block smem candidate buffer
#define SELC   24576      // smem-resident (key+idx) cap in k_select

static __device__ __forceinline__ float clampf(float x) {
    return fminf(fmaxf(x, 1e-3f), 0.999f);
}

// ---------------- scratch ----------------
__device__ float        d_tab[2][BATCH][112];         // Ev[16] Et[32] Eh[32] Ew[32]
__device__ int          d_Kc[2];
__device__ int          d_bHi[ROWS];
__device__ int          d_bLo[ROWS];
__device__ unsigned int d_abovePart[ROWS][NSEG];
__device__ unsigned int d_ccPart[ROWS][NSEG];
__device__ unsigned int d_candKey[ROWS][NSEG * CAPB]; // 16 MB
__device__ unsigned int d_candIdx[ROWS][NSEG * CAPB]; // 16 MB

// ---------------- k_histscan: tables + sampled hist (1/8) + suffix scan, 1 block/row ----------------
__global__ void __launch_bounds__(1024) k_histscan(
    const float* __restrict__ comps, const int* __restrict__ idxp,
    const float* __restrict__ ur_s, const float* __restrict__ ur_t,
    const float* __restrict__ uv_s, const float* __restrict__ ut_s,
    const float* __restrict__ uh_s, const float* __restrict__ uw_s,
    const float* __restrict__ uv_t, const float* __restrict__ ut_t,
    const float* __restrict__ uh_t, const float* __restrict__ uw_t,
    const float* __restrict__ u0s, const float* __restrict__ u0t)
{
    __shared__ unsigned int sh[NB1];
    __shared__ float stab[112];
    __shared__ unsigned int wsum[32];
    __shared__ unsigned int stot;
    int row  = blockIdx.x;
    int side = row >> 5, b = row & 31;
    int t = threadIdx.x;
    for (int i = t; i < NB1; i += 1024) sh[i] = 0u;

    // compute this row's pow-table (also publish for k_mask)
    if (t < 112) {
        int id = idxp[0];
        const float* uv = side ? uv_t : uv_s;
        const float* ut = side ? ut_t : ut_s;
        const float* uh = side ? uh_t : uh_s;
        const float* uw = side ? uw_t : uw_s;
        float val, ia;
        if (t < 16)      { val = uv[b*16 +  t     ]; ia = 1.0f / comps[id*4+0]; }
        else if (t < 48) { val = ut[b*32 + (t-16)]; ia = 1.0f / comps[id*4+1]; }
        else if (t < 80) { val = uh[b*32 + (t-48)]; ia = 1.0f / comps[id*4+2]; }
        else             { val = uw[b*32 + (t-80)]; ia = 1.0f / comps[id*4+3]; }
        float e = powf(clampf(val), ia);
        stab[t] = e;
        d_tab[side][b][t] = e;
    }
    if (row == 0 && t == 0) d_Kc[0] = (int)(clampf(ur_s[0]) * (float)NTOK);
    if (row == 0 && t == 1) d_Kc[1] = (int)(clampf(ur_t[0]) * (float)NTOK);
    __syncthreads();

    const float4* src = (const float4*)((side ? u0t : u0s) + (size_t)b * NTOK);
    int q = t & 3;
    int w = q * 8;

    auto chunk_b4 = [&](int ch) -> int {
        int g  = ch * 256 + (t >> 2);
        int v  = g >> 7, tt = (g >> 2) & 31, j = g & 3;
        int h  = (v*3 + tt*5 + j*8) & 31;
        return ((((v << 5) | tt) << 5) | h) * 8 + q * 2;
    };
    auto chunk_pre = [&](int ch) -> float {
        int g  = ch * 256 + (t >> 2);
        int v  = g >> 7, tt = (g >> 2) & 31, j = g & 3;
        int h  = (v*3 + tt*5 + j*8) & 31;
        return stab[v] * stab[16+tt] * stab[48+h];
    };

    // prologue: load chunks 0 and 1 (depth-2 register pipeline)
    int b40 = chunk_b4(0);
    float4 A0 = src[b40];
    float4 C0 = src[b40 + 1];
    int b41 = chunk_b4(1);
    float4 A1 = src[b41];
    float4 C1 = src[b41 + 1];
    float pre0 = chunk_pre(0);
    float pre1 = chunk_pre(1);

    for (int ch = 0; ch < 8; ch++) {
        float4 A2, C2;
        float pre2 = 0.0f;
        if (ch + 2 < 8) {
            int b4 = chunk_b4(ch + 2);
            A2 = src[b4];
            C2 = src[b4 + 1];
            pre2 = chunk_pre(ch + 2);
        }

        float pre = pre0;
        float k0 = clampf(A0.x) * pre * stab[80+w+0];
        float k1 = clampf(A0.y) * pre * stab[80+w+1];
        float k2 = clampf(A0.z) * pre * stab[80+w+2];
        float k3 = clampf(A0.w) * pre * stab[80+w+3];
        float k4 = clampf(C0.x) * pre * stab[80+w+4];
        float k5 = clampf(C0.y) * pre * stab[80+w+5];
        float k6 = clampf(C0.z) * pre * stab[80+w+6];
        float k7 = clampf(C0.w) * pre * stab[80+w+7];
        atomicAdd(&sh[__float_as_uint(k0) >> 19], 1u);
        atomicAdd(&sh[__float_as_uint(k1) >> 19], 1u);
        atomicAdd(&sh[__float_as_uint(k2) >> 19], 1u);
        atomicAdd(&sh[__float_as_uint(k3) >> 19], 1u);
        atomicAdd(&sh[__float_as_uint(k4) >> 19], 1u);
        atomicAdd(&sh[__float_as_uint(k5) >> 19], 1u);
        atomicAdd(&sh[__float_as_uint(k6) >> 19], 1u);
        atomicAdd(&sh[__float_as_uint(k7) >> 19], 1u);

        A0 = A1; C0 = C1; pre0 = pre1;
        A1 = A2; C1 = C2; pre1 = pre2;
    }
    __syncthreads();

    // suffix scan over descending buckets
    unsigned int v[8]; unsigned int s = 0;
    #pragma unroll
    for (int i = 0; i < 8; i++) { v[i] = sh[8191 - (t*8 + i)]; s += v[i]; }
    unsigned int x = s;
    int lane = t & 31, wp = t >> 5;
    #pragma unroll
    for (int o = 1; o < 32; o <<= 1) {
        unsigned int y = __shfl_up_sync(0xffffffffu, x, o);
        if (lane >= o) x += y;
    }
    if (lane == 31) wsum[wp] = x;
    __syncthreads();
    if (t < 32) {
        unsigned int y = wsum[t], z = y;
        #pragma unroll
        for (int o = 1; o < 32; o <<= 1) {
            unsigned int qq = __shfl_up_sync(0xffffffffu, z, o);
            if (t >= o) z += qq;
        }
        wsum[t] = z - y;                 // exclusive warp prefix
        if (t == 31) stot = z;
    }
    __syncthreads();
    unsigned int P = wsum[wp] + x - s;   // samples strictly above this thread's chunk
    float urv = side ? ur_t[0] : ur_s[0];
    unsigned int K = (unsigned int)(int)(clampf(urv) * (float)NTOK);
    unsigned int sKt = K >> 3;           // sample fraction exactly 1/8
    unsigned int targHi = (sKt > SMARG) ? (sKt - SMARG) : 0u;
    unsigned int targLo = sKt + SMARG;
    unsigned int total = stot;
    unsigned int cum = P;
    #pragma unroll
    for (int i = 0; i < 8; i++) {
        int bb = 8191 - (t*8 + i);
        unsigned int hv = v[i];
        if (cum <= targHi && cum + hv > targHi) d_bHi[row] = bb;
        if (cum <  targLo && cum + hv >= targLo) d_bLo[row] = bb;
        cum += hv;
    }
    if (t == 0 && targLo > total) d_bLo[row] = 0;
}

// ---------------- k_mask: pipelined loads, aggregated append, single end-flush ----------------
extern __shared__ unsigned int mbuf[];
__global__ void __launch_bounds__(512, 2) k_mask(const float* __restrict__ u0s,
                                                 const float* __restrict__ u0t,
                                                 float* __restrict__ out)
{
    __shared__ float stab[112];
    __shared__ unsigned int s17[17];
    __shared__ unsigned int sCnt;
    unsigned int* bKey = mbuf;
    unsigned int* bIdx = mbuf + BUFCAP;

    int row   = blockIdx.x >> 3;
    int chunk = blockIdx.x & 7;
    int side  = row >> 5, b = row & 31;
    int t = threadIdx.x;
    if (t < 112) stab[t] = d_tab[side][b][t];
    if (t == 0) sCnt = 0u;
    __syncthreads();

    unsigned int bHi = (unsigned int)d_bHi[row];
    unsigned int bLo = (unsigned int)d_bLo[row];
    unsigned long long hk = ((unsigned long long)(bHi + 1)) << 19;
    float Thif = (hk >= 0x3F800000ull) ? 1.0f : __uint_as_float((unsigned int)hk);
    float Tlof = __uint_as_float(bLo << 19);

    const float4* src = (const float4*)((side ? u0t : u0s) + (size_t)b * NTOK);
    float4* out4 = (float4*)(out + (size_t)row * NTOK);
    unsigned int* segK = &d_candKey[row][chunk * CAPB];
    unsigned int* segI = &d_candIdx[row][chunk * CAPB];
    int lane = t & 31;
    unsigned int lmask = (1u << lane) - 1u;
    unsigned int nAbove = 0;

    int w0 = (t << 2) & 31;
    int h  = (t >> 3) & 31;
    float hC = stab[48 + h];
    float wj0 = stab[80+w0+0] * hC;
    float wj1 = stab[80+w0+1] * hC;
    float wj2 = stab[80+w0+2] * hC;
    float wj3 = stab[80+w0+3] * hC;

#define PROC(u, idx4) do {                                                          \
    float pre = stab[(idx4) >> 13] * stab[16 + (((idx4) >> 8) & 31)];               \
    float k0 = clampf((u).x) * pre * wj0;                                           \
    float k1 = clampf((u).y) * pre * wj1;                                           \
    float k2 = clampf((u).z) * pre * wj2;                                           \
    float k3 = clampf((u).w) * pre * wj3;                                           \
    bool a0 = (k0 >= Thif), a1 = (k1 >= Thif), a2 = (k2 >= Thif), a3 = (k3 >= Thif);\
    nAbove += (unsigned int)a0 + a1 + a2 + a3;                                      \
    unsigned int cm = (unsigned int)(!a0 && k0 >= Tlof)                             \
                    | ((unsigned int)(!a1 && k1 >= Tlof) << 1)                      \
                    | ((unsigned int)(!a2 && k2 >= Tlof) << 2)                      \
                    | ((unsigned int)(!a3 && k3 >= Tlof) << 3);                     \
    unsigned int b0 = __ballot_sync(0xffffffffu, cm & 1u);                          \
    unsigned int b1 = __ballot_sync(0xffffffffu, cm & 2u);                          \
    unsigned int b2 = __ballot_sync(0xffffffffu, cm & 4u);                          \
    unsigned int b3 = __ballot_sync(0xffffffffu, cm & 8u);                          \
    unsigned int c0 = __popc(b0), c1 = __popc(b1), c2 = __popc(b2), c3 = __popc(b3);\
    unsigned int tot = c0 + c1 + c2 + c3;                                           \
    if (tot) {                                                                      \
        unsigned int bp = 0;                                                        \
        if (lane == 0) bp = atomicAdd(&sCnt, tot);                                  \
        bp = __shfl_sync(0xffffffffu, bp, 0);                                       \
        int n = (idx4) << 2;                                                        \
        if (cm & 1u) { unsigned int p = bp + __popc(b0 & lmask);                    \
            if (p < BUFCAP) { bKey[p] = __float_as_uint(k0); bIdx[p] = (unsigned int)n; } } \
        if (cm & 2u) { unsigned int p = bp + c0 + __popc(b1 & lmask);               \
            if (p < BUFCAP) { bKey[p] = __float_as_uint(k1); bIdx[p] = (unsigned int)(n + 1); } } \
        if (cm & 4u) { unsigned int p = bp + c0 + c1 + __popc(b2 & lmask);          \
            if (p < BUFCAP) { bKey[p] = __float_as_uint(k2); bIdx[p] = (unsigned int)(n + 2); } } \
        if (cm & 8u) { unsigned int p = bp + c0 + c1 + c2 + __popc(b3 & lmask);     \
            if (p < BUFCAP) { bKey[p] = __float_as_uint(k3); bIdx[p] = (unsigned int)(n + 3); } } \
    }                                                                               \
    __stcs(&out4[(idx4)], make_float4(a0 ? 1.0f : 0.0f, a1 ? 1.0f : 0.0f,           \
                                      a2 ? 1.0f : 0.0f, a3 ? 1.0f : 0.0f));         \
} while (0)

    int base4 = chunk * 16384;

    // prologue: load group 0
    int i0 = base4 + t;
    float4 u0 = __ldcs(&src[i0]);
    float4 u1 = __ldcs(&src[i0 + 512]);
    float4 u2 = __ldcs(&src[i0 + 1024]);
    float4 u3 = __ldcs(&src[i0 + 1536]);

    for (int itg = 0; itg < 8; itg++) {
        int j0 = base4 + (itg + 1) * 2048 + t;
        float4 n0, n1, n2, n3;
        if (itg < 7) { n0 = __ldcs(&src[j0]); n1 = __ldcs(&src[j0 + 512]); }
        PROC(u0, i0);
        PROC(u1, i0 + 512);
        if (itg < 7) { n2 = __ldcs(&src[j0 + 1024]); n3 = __ldcs(&src[j0 + 1536]); }
        PROC(u2, i0 + 1024);
        PROC(u3, i0 + 1536);
        u0 = n0; u1 = n1; u2 = n2; u3 = n3;
        i0 = j0;
    }
#undef PROC

    // single flush at end (per-segment candidates ~2050 mean at 1/8, >200 sigma below BUFCAP)
    __syncthreads();
    unsigned int cur = sCnt;
    if (cur > BUFCAP) cur = BUFCAP;
    for (unsigned int i = t; i < cur; i += 512) {
        if (i < CAPB) { segK[i] = bKey[i]; segI[i] = bIdx[i]; }
    }

    unsigned int wv = __reduce_add_sync(0xffffffffu, nAbove);
    if (lane == 0) s17[t >> 5] = wv;
    __syncthreads();
    if (t < 16) {
        unsigned int z = s17[t];
        #pragma unroll
        for (int o = 8; o > 0; o >>= 1) z += __shfl_down_sync(0xffffu, z, o);
        if (t == 0) d_abovePart[row][chunk] = z;
    }
    if (t == 16) d_ccPart[row][chunk] = (cur < CAPB) ? cur : CAPB;
}

// ---------------- block reduce helper (fallback path only) ----------------
static __device__ __forceinline__ unsigned int blk_reduce_1024(unsigned int v, unsigned int* s33)
{
    unsigned int wv = __reduce_add_sync(0xffffffffu, v);
    int lane = threadIdx.x & 31, w = threadIdx.x >> 5;
    __syncthreads();
    if (lane == 0) s33[w] = wv;
    __syncthreads();
    if (threadIdx.x < 32) {
        unsigned int x = s33[threadIdx.x];
        x = __reduce_add_sync(0xffffffffu, x);
        if (threadIdx.x == 0) s33[32] = x;
    }
    __syncthreads();
    return s33[32];
}

// ---------------- k_select: smem-resident keys+idx, radix descent + tie-break ----------------
extern __shared__ unsigned int dynsm[];
__global__ void __launch_bounds__(1024) k_select(float* __restrict__ out)
{
    __shared__ unsigned int hcnt[1024];
    __shared__ unsigned int wsum[32];
    __shared__ unsigned int sSel, sRnew;
    __shared__ unsigned int eqIdx[2048];
    __shared__ unsigned int eqCnt;
    __shared__ unsigned int sIstar;
    __shared__ unsigned int s33[33];
    unsigned int* keys = dynsm;
    unsigned int* idxs = dynsm + SELC;

    int row = blockIdx.x, t = threadIdx.x;
    unsigned int cnt[NSEG], off[NSEG];
    unsigned int c = 0, above = 0;
    #pragma unroll
    for (int s = 0; s < NSEG; s++) {
        unsigned int cs = d_ccPart[row][s];
        cnt[s] = (cs < CAPB) ? cs : CAPB;
        off[s] = c;
        c += cnt[s];
        above += d_abovePart[row][s];
    }
    unsigned int K = (unsigned int)d_Kc[row >> 5];
    int R = (int)K - (int)above;
    const unsigned int* gk = d_candKey[row];
    const unsigned int* gi = d_candIdx[row];
    float* orow = out + (size_t)row * NTOK;
    if (R <= 0) return;
    if ((unsigned int)R >= c) {
        #pragma unroll
        for (int s = 0; s < NSEG; s++)
            for (unsigned int i = t; i < cnt[s]; i += 1024)
                orow[gi[s*CAPB + i]] = 1.0f;
        return;
    }

    bool insm = (c <= SELC);
    if (insm) {
        #pragma unroll
        for (int s = 0; s < NSEG; s++)
            for (unsigned int i = t; i < cnt[s]; i += 1024) {
                keys[off[s] + i] = gk[s*CAPB + i];
                idxs[off[s] + i] = gi[s*CAPB + i];
            }
        __syncthreads();
    }

    unsigned int bLo = (unsigned int)d_bLo[row], bHi = (unsigned int)d_bHi[row];
    unsigned int base = bLo << 19;
    unsigned long long Wd = ((unsigned long long)(bHi + 1u - bLo)) << 19;
    int sb = (Wd <= 1ull) ? 0 : (64 - __clzll(Wd - 1ull));
    if (sb > 32) sb = 32;
    unsigned int Rcur = (unsigned int)R;

    while (sb > 0) {
        int bits = sb >= 10 ? 10 : sb;
        int shift = sb - bits;
        hcnt[t] = 0u;
        __syncthreads();
        unsigned int spanm = (sb >= 32) ? 0xFFFFFFFFu : ((1u << sb) - 1u);
        if (insm) {
            for (unsigned int i = t; i < c; i += 1024) {
                unsigned int k = keys[i];
                unsigned int d = k - base;
                if (k >= base && d <= spanm) atomicAdd(&hcnt[d >> shift], 1u);
            }
        } else {
            #pragma unroll
            for (int s = 0; s < NSEG; s++)
                for (unsigned int i = t; i < cnt[s]; i += 1024) {
                    unsigned int k = gk[s*CAPB + i];
                    unsigned int d = k - base;
                    if (k >= base && d <= spanm) atomicAdd(&hcnt[d >> shift], 1u);
                }
        }
        __syncthreads();
        unsigned int x = hcnt[1023 - t];
        unsigned int cb = x;
        int lane = t & 31, w = t >> 5;
        #pragma unroll
        for (int o = 1; o < 32; o <<= 1) {
            unsigned int y = __shfl_up_sync(0xffffffffu, x, o);
            if (lane >= o) x += y;
        }
        if (lane == 31) wsum[w] = x;
        __syncthreads();
        if (t < 32) {
            unsigned int y = wsum[t], z = y;
            #pragma unroll
            for (int o = 1; o < 32; o <<= 1) {
                unsigned int q = __shfl_up_sync(0xffffffffu, z, o);
                if (t >= o) z += q;
            }
            wsum[t] = z - y;
        }
        __syncthreads();
        unsigned int incl = wsum[w] + x;
        unsigned int A = incl - cb;
        if (A < Rcur && Rcur <= incl) { sSel = (unsigned int)(1023 - t); sRnew = Rcur - A; }
        __syncthreads();
        base += sSel << shift;
        Rcur = sRnew;
        sb = shift;
        __syncthreads();
    }
    unsigned int Tkey = base;
    unsigned int R3 = Rcur;   // rank among equal keys (stable by index), >= 1

    if (t == 0) eqCnt = 0u;
    __syncthreads();
    if (insm) {
        for (unsigned int i = t; i < c; i += 1024)
            if (keys[i] == Tkey) {
                unsigned int p = atomicAdd(&eqCnt, 1u);
                if (p < 2048) eqIdx[p] = idxs[i];
            }
    } else {
        #pragma unroll
        for (int s = 0; s < NSEG; s++)
            for (unsigned int i = t; i < cnt[s]; i += 1024)
                if (gk[s*CAPB + i] == Tkey) {
                    unsigned int p = atomicAdd(&eqCnt, 1u);
                    if (p < 2048) eqIdx[p] = gi[s*CAPB + i];
                }
    }
    __syncthreads();
    unsigned int e = eqCnt;
    unsigned int Istar;
    if (e <= 2048) {
        for (unsigned int j = t; j < e; j += 1024) {
            unsigned int my = eqIdx[j], r = 0;
            for (unsigned int m = 0; m < e; m++) r += (eqIdx[m] < my);
            if (r == R3 - 1u) sIstar = my;
        }
        __syncthreads();
        Istar = sIstar;
    } else {
        unsigned int ilo = 0, ihi = NTOK - 1;
        while (ilo < ihi) {
            unsigned int mid = (ilo + ihi) >> 1;
            unsigned int l2 = 0;
            if (insm) {
                for (unsigned int i = t; i < c; i += 1024)
                    if (keys[i] == Tkey) l2 += (idxs[i] <= mid);
            } else {
                #pragma unroll
                for (int s = 0; s < NSEG; s++)
                    for (unsigned int i = t; i < cnt[s]; i += 1024)
                        if (gk[s*CAPB + i] == Tkey) l2 += (gi[s*CAPB + i] <= mid);
            }
            unsigned int cc2 = blk_reduce_1024(l2, s33);
            if (cc2 >= R3) ihi = mid; else ilo = mid + 1u;
        }
        Istar = ilo;
    }

    if (insm) {
        for (unsigned int i = t; i < c; i += 1024) {
            unsigned int k = keys[i];
            if (k > Tkey || (k == Tkey && idxs[i] <= Istar)) orow[idxs[i]] = 1.0f;
        }
    } else {
        #pragma unroll
        for (int s = 0; s < NSEG; s++)
            for (unsigned int i = t; i < cnt[s]; i += 1024) {
                unsigned int k = gk[s*CAPB + i];
                if (k > Tkey || (k == Tkey && gi[s*CAPB + i] <= Istar))
                    orow[gi[s*CAPB + i]] = 1.0f;
            }
    }
}

// ---------------- launch ----------------
extern "C" void kernel_launch(void* const* d_in, const int* in_sizes, int n_in,
                              void* d_out, int out_size)
{
    const float* comps = (const float*)d_in[0];
    const float* ur_s  = (const float*)d_in[1];
    const float* ur_t  = (const float*)d_in[2];
    const float* u0s   = (const float*)d_in[3];
    const float* u0t   = (const float*)d_in[4];
    const float* uv_s  = (const float*)d_in[5];
    const float* ut_s  = (const float*)d_in[6];
    const float* uh_s  = (const float*)d_in[7];
    const float* uw_s  = (const float*)d_in[8];
    const float* uv_t  = (const float*)d_in[9];
    const float* ut_t  = (const float*)d_in[10];
    const float* uh_t  = (const float*)d_in[11];
    const float* uw_t  = (const float*)d_in[12];
    const int*   idx   = (const int*)d_in[13];
    float* out = (float*)d_out;

    static int attr_done = 0;
    if (!attr_done) {
        cudaFuncSetAttribute(k_mask, cudaFuncAttributeMaxDynamicSharedMemorySize,
                             BUFCAP * 2 * sizeof(unsigned int));
        cudaFuncSetAttribute(k_select, cudaFuncAttributeMaxDynamicSharedMemorySize,
                             SELC * 2 * sizeof(unsigned int));
        attr_done = 1;
    }

    k_histscan<<<64, 1024>>>(comps, idx, ur_s, ur_t,
                             uv_s, ut_s, uh_s, uw_s,
                             uv_t, ut_t, uh_t, uw_t,
                             u0s, u0t);
    k_mask<<<512, 512, BUFCAP * 2 * sizeof(unsigned int)>>>(u0s, u0t, out);
    k_select<<<64, 1024, SELC * 2 * sizeof(unsigned int)>>>(out);
}